// round 1
// baseline (speedup 1.0000x reference)
#include <cuda_runtime.h>
#include <math.h>

#define N_DIM 64
#define B_ROWS 1024
#define TPB 256
#define ROWS_PER_BLOCK 2
#define JTILE 128
#define NCHUNK (B_ROWS / TPB)   // 4 query chunks per column

// Scratch (device globals — no allocation allowed)
__device__ float g_logrho[B_ROWS];
__device__ float g_partials[N_DIM * NCHUNK];

// ---------------------------------------------------------------------------
// Kernel 1: per-row kth-NN squared distance -> log(rho_sq)
// grid = B_ROWS / ROWS_PER_BLOCK blocks, TPB threads
// ---------------------------------------------------------------------------
__global__ void knn_kernel(const float* __restrict__ act, const int* __restrict__ kp) {
    __shared__ float xi[ROWS_PER_BLOCK][N_DIM];
    __shared__ float dist[ROWS_PER_BLOCK][B_ROWS];
    __shared__ float tile[JTILE][N_DIM + 1];   // +1 pad: kills 32-way bank conflicts
    __shared__ float rmin[TPB];
    __shared__ int   ridx[TPB];

    const int tid = threadIdx.x;
    const int row0 = blockIdx.x * ROWS_PER_BLOCK;

    // load this block's query rows
    for (int idx = tid; idx < ROWS_PER_BLOCK * N_DIM; idx += TPB)
        xi[idx / N_DIM][idx % N_DIM] = act[(row0 + idx / N_DIM) * N_DIM + (idx % N_DIM)];

    // pairwise distances via coalesced j-tiles
    for (int tb = 0; tb < B_ROWS; tb += JTILE) {
        __syncthreads();
        for (int idx = tid; idx < JTILE * N_DIM; idx += TPB) {
            int r = idx / N_DIM, c = idx % N_DIM;
            tile[r][c] = act[(tb + r) * N_DIM + c];
        }
        __syncthreads();
        const int jj = tid & (JTILE - 1);
        const int rr = tid >> 7;               // TPB/JTILE = 2 rows
        float s = 0.0f;
        #pragma unroll 16
        for (int d = 0; d < N_DIM; d++) {
            float df = xi[rr][d] - tile[jj][d];
            s = fmaf(df, df, s);
        }
        dist[rr][tb + jj] = s;
    }
    __syncthreads();

    const int k = *kp;
    for (int rr = 0; rr < ROWS_PER_BLOCK; rr++) {
        float rho = 0.0f;   // thread 0 keeps the current extracted min
        for (int pass = 0; pass <= k; pass++) {
            float mv = 3.4e38f; int mi = 0;
            for (int j = tid; j < B_ROWS; j += TPB) {
                float v = dist[rr][j];
                if (v < mv) { mv = v; mi = j; }
            }
            rmin[tid] = mv; ridx[tid] = mi;
            __syncthreads();
            for (int st = TPB / 2; st > 0; st >>= 1) {
                if (tid < st && rmin[tid + st] < rmin[tid]) {
                    rmin[tid] = rmin[tid + st];
                    ridx[tid] = ridx[tid + st];
                }
                __syncthreads();
            }
            if (tid == 0) {
                rho = rmin[0];
                dist[rr][ridx[0]] = 3.4e38f;   // remove for next pass
            }
            __syncthreads();
        }
        if (tid == 0)
            g_logrho[row0 + rr] = logf(fmaxf(rho, 1e-12f));
        __syncthreads();
    }
}

// ---------------------------------------------------------------------------
// Kernel 2: KDE marginal entropy partial sums
// grid = (N_DIM, NCHUNK), TPB threads; each thread owns exactly one query
// ---------------------------------------------------------------------------
__global__ void kde_kernel(const float* __restrict__ act) {
    __shared__ float a[B_ROWS];
    __shared__ float red[TPB];
    __shared__ float stat[2];

    const int tid = threadIdx.x;
    const int r = blockIdx.x;
    const int chunk = blockIdx.y;

    float s1 = 0.0f, s2 = 0.0f;
    float vloc[NCHUNK];
    #pragma unroll
    for (int t = 0; t < NCHUNK; t++) {
        int j = tid + t * TPB;
        float v = act[j * N_DIM + r];
        a[j] = v;
        vloc[t] = v;
        s1 += v;
        s2 += v * v;
    }

    // reduce sum
    red[tid] = s1; __syncthreads();
    for (int st = TPB / 2; st > 0; st >>= 1) {
        if (tid < st) red[tid] += red[tid + st];
        __syncthreads();
    }
    if (tid == 0) stat[0] = red[0];
    __syncthreads();
    // reduce sum of squares
    red[tid] = s2; __syncthreads();
    for (int st = TPB / 2; st > 0; st >>= 1) {
        if (tid < st) red[tid] += red[tid + st];
        __syncthreads();
    }
    if (tid == 0) stat[1] = red[0];
    __syncthreads();

    const float Bf = (float)B_ROWS;
    float mean = stat[0] / Bf;
    float var = (stat[1] - Bf * mean * mean) / (Bf - 1.0f);
    float stdv = sqrtf(fmaxf(var, 0.0f));
    float h = fmaxf(1.06f * stdv * powf(Bf, -0.2f), 1e-4f);
    float inv_h = 1.0f / h;

    // scale samples in place: a[j] = x_j / h
    #pragma unroll
    for (int t = 0; t < NCHUNK; t++)
        a[tid + t * TPB] = vloc[t] * inv_h;
    __syncthreads();

    const float c = 2.0f * inv_h;
    const float x = a[chunk * TPB + tid];

    float e0 = 0.0f, e1 = 0.0f, e2 = 0.0f;
    #pragma unroll 4
    for (int j = 0; j < B_ROWS; j++) {
        float aj = a[j];           // broadcast (all lanes same j)
        float d = x - aj;
        float s = x + aj;
        float t3 = s - c;
        e0 += __expf(-0.5f * d * d);
        e1 += __expf(-0.5f * s * s);
        e2 += __expf(-0.5f * t3 * t3);
    }
    // density = sum_kernels / (sqrt(2*pi) * B * h)
    const float scale = inv_h * (1.0f / (Bf * 2.5066282746310002f));
    float dens = (e0 + e1 + e2) * scale;
    float l = logf(dens + 1e-8f);

    red[tid] = l; __syncthreads();
    for (int st = TPB / 2; st > 0; st >>= 1) {
        if (tid < st) red[tid] += red[tid + st];
        __syncthreads();
    }
    if (tid == 0)
        g_partials[r * NCHUNK + chunk] = red[0];
}

// ---------------------------------------------------------------------------
// Kernel 3: assemble output
// ---------------------------------------------------------------------------
__global__ void final_kernel(const int* __restrict__ kp, float* __restrict__ out) {
    __shared__ double dred[TPB];
    const int tid = threadIdx.x;

    double s = 0.0;
    for (int j = tid; j < B_ROWS; j += TPB) s += (double)g_logrho[j];
    dred[tid] = s; __syncthreads();
    for (int st = TPB / 2; st > 0; st >>= 1) {
        if (tid < st) dred[tid] += dred[tid + st];
        __syncthreads();
    }

    if (tid == 0) {
        const int k = *kp;
        const double EULER = 0.5772156649015328606;
        double dg_k = -EULER;
        for (int i = 1; i < k; i++) dg_k += 1.0 / (double)i;
        double dg_B = -EULER;
        for (int i = 1; i < B_ROWS; i++) dg_B += 1.0 / (double)i;
        double log_c_d = 0.5 * (double)N_DIM * log(M_PI) - lgamma((double)N_DIM * 0.5 + 1.0);
        double mean_lr = dred[0] / (double)B_ROWS;
        double h_nats = -dg_k + dg_B + log_c_d + (double)N_DIM * 0.5 * mean_lr;
        out[0] = (float)(h_nats / log(2.0));
    }
    if (tid < N_DIM) {
        float t = 0.0f;
        #pragma unroll
        for (int cch = 0; cch < NCHUNK; cch++)
            t += g_partials[tid * NCHUNK + cch];
        out[1 + tid] = -t / (float)B_ROWS;
    }
}

// ---------------------------------------------------------------------------
extern "C" void kernel_launch(void* const* d_in, const int* in_sizes, int n_in,
                              void* d_out, int out_size) {
    const float* act = (const float*)d_in[0];
    const int*   kp  = (const int*)d_in[1];
    float* out = (float*)d_out;
    (void)in_sizes; (void)n_in; (void)out_size;

    knn_kernel<<<B_ROWS / ROWS_PER_BLOCK, TPB>>>(act, kp);
    dim3 g(N_DIM, NCHUNK);
    kde_kernel<<<g, TPB>>>(act);
    final_kernel<<<1, TPB>>>(kp, out);
}

// round 2
// speedup vs baseline: 1.5410x; 1.5410x over previous
#include <cuda_runtime.h>
#include <math.h>

#define N_DIM   64
#define B_ROWS  1024
#define QCHUNKS 16                 // kde query chunks of 64
#define THRESH  6.5f               // truncation radius in bandwidth units: exp(-21.1) dropped

// Scratch (device globals — no allocation allowed)
__device__ float g_logrho[B_ROWS];
__device__ float g_cols[N_DIM * B_ROWS];     // sorted, scaled (x/h) columns
__device__ float g_invh[N_DIM];
__device__ float g_partials[N_DIM * QCHUNKS];

__device__ __forceinline__ float ex2(float x) {
    float r;
    asm("ex2.approx.ftz.f32 %0, %1;" : "=f"(r) : "f"(x));
    return r;
}

// ---------------------------------------------------------------------------
// Kernel 1: kNN — one warp per row, register top-8, warp-shuffle merge.
// grid = 128, block = 256 (8 warps -> 8 rows)
// ---------------------------------------------------------------------------
__global__ __launch_bounds__(256, 1)
void knn_kernel(const float* __restrict__ act, const int* __restrict__ kp) {
    __shared__ float tile[128][68];        // stride 68 floats: conflict-free LDS.128
    __shared__ float xq[8][N_DIM];

    const int tid  = threadIdx.x;
    const int lane = tid & 31;
    const int w    = tid >> 5;             // warp id = local row
    const int row0 = blockIdx.x * 8;

    // load this block's 8 query rows into shared
    for (int idx = tid; idx < 8 * N_DIM; idx += 256)
        xq[idx >> 6][idx & 63] = act[(row0 + (idx >> 6)) * N_DIM + (idx & 63)];

    float m[8];
    #pragma unroll
    for (int i = 0; i < 8; i++) m[i] = 3.4e38f;

    for (int tb = 0; tb < B_ROWS; tb += 128) {
        __syncthreads();
        // cooperative coalesced tile load (128 rows x 64 dims), float4
        const float4* gsrc = (const float4*)(act + tb * N_DIM);
        #pragma unroll
        for (int t = 0; t < 8; t++) {
            int fi = tid + t * 256;        // 0..2047 float4s
            int r  = fi >> 4;
            int c  = fi & 15;
            *((float4*)&tile[r][c * 4]) = gsrc[fi];
        }
        __syncthreads();

        float acc[4] = {0.f, 0.f, 0.f, 0.f};
        #pragma unroll
        for (int c = 0; c < 4; c++) {      // 4 chunks of 16 dims
            const float4 q0 = *(const float4*)&xq[w][c * 16 + 0];
            const float4 q1 = *(const float4*)&xq[w][c * 16 + 4];
            const float4 q2 = *(const float4*)&xq[w][c * 16 + 8];
            const float4 q3 = *(const float4*)&xq[w][c * 16 + 12];
            #pragma unroll
            for (int s = 0; s < 4; s++) {
                const int j = lane + 32 * s;
                const float4 b0 = *(const float4*)&tile[j][c * 16 + 0];
                const float4 b1 = *(const float4*)&tile[j][c * 16 + 4];
                const float4 b2 = *(const float4*)&tile[j][c * 16 + 8];
                const float4 b3 = *(const float4*)&tile[j][c * 16 + 12];
                float a = acc[s];
                float d;
                d = q0.x - b0.x; a = fmaf(d, d, a);
                d = q0.y - b0.y; a = fmaf(d, d, a);
                d = q0.z - b0.z; a = fmaf(d, d, a);
                d = q0.w - b0.w; a = fmaf(d, d, a);
                d = q1.x - b1.x; a = fmaf(d, d, a);
                d = q1.y - b1.y; a = fmaf(d, d, a);
                d = q1.z - b1.z; a = fmaf(d, d, a);
                d = q1.w - b1.w; a = fmaf(d, d, a);
                d = q2.x - b2.x; a = fmaf(d, d, a);
                d = q2.y - b2.y; a = fmaf(d, d, a);
                d = q2.z - b2.z; a = fmaf(d, d, a);
                d = q2.w - b2.w; a = fmaf(d, d, a);
                d = q3.x - b3.x; a = fmaf(d, d, a);
                d = q3.y - b3.y; a = fmaf(d, d, a);
                d = q3.z - b3.z; a = fmaf(d, d, a);
                d = q3.w - b3.w; a = fmaf(d, d, a);
                acc[s] = a;
            }
        }

        // insert 4 candidates into per-lane sorted top-8 (registers only)
        #pragma unroll
        for (int s = 0; s < 4; s++) {
            float v = acc[s];
            if (v < m[7]) {
                m[7] = v;
                #pragma unroll
                for (int i = 7; i > 0; i--) {
                    if (m[i] < m[i - 1]) { float t2 = m[i]; m[i] = m[i - 1]; m[i - 1] = t2; }
                }
            }
        }
    }

    // warp merge: extract (k+1) global minima from 32 sorted lists
    const int kk = *kp;
    float rho = 0.f;
    for (int r = 0; r <= kk && r < 8; r++) {
        float mv = m[0];
        #pragma unroll
        for (int off = 16; off; off >>= 1)
            mv = fminf(mv, __shfl_xor_sync(0xffffffffu, mv, off));
        rho = mv;
        unsigned msk = __ballot_sync(0xffffffffu, m[0] == mv);
        if (lane == (__ffs(msk) - 1)) {
            #pragma unroll
            for (int i = 0; i < 7; i++) m[i] = m[i + 1];
            m[7] = 3.4e38f;
        }
    }
    if (lane == 0)
        g_logrho[row0 + w] = logf(fmaxf(rho, 1e-12f));
}

// ---------------------------------------------------------------------------
// Kernel 2: per-column prep — std -> h, scale by 1/h, bitonic sort, store.
// grid = 64, block = 256
// ---------------------------------------------------------------------------
__global__ void prep_kernel(const float* __restrict__ act) {
    __shared__ float u[B_ROWS];
    __shared__ float red[256];
    __shared__ float sh_invh;

    const int tid = threadIdx.x;
    const int col = blockIdx.x;

    float s1 = 0.f, s2 = 0.f;
    #pragma unroll
    for (int t = 0; t < 4; t++) {
        float v = act[(tid + 256 * t) * N_DIM + col];
        u[tid + 256 * t] = v;
        s1 += v;
        s2 += v * v;
    }
    // reduce s1
    red[tid] = s1; __syncthreads();
    for (int st = 128; st > 0; st >>= 1) {
        if (tid < st) red[tid] += red[tid + st];
        __syncthreads();
    }
    float tot1 = red[0]; __syncthreads();
    red[tid] = s2; __syncthreads();
    for (int st = 128; st > 0; st >>= 1) {
        if (tid < st) red[tid] += red[tid + st];
        __syncthreads();
    }
    if (tid == 0) {
        const float Bf = (float)B_ROWS;
        float mean = tot1 / Bf;
        float var  = (red[0] - Bf * mean * mean) / (Bf - 1.0f);
        float stdv = sqrtf(fmaxf(var, 0.f));
        float h    = fmaxf(1.06f * stdv * 0.25f, 1e-4f);  // 1024^(-0.2) = 0.25
        float ih   = 1.0f / h;
        sh_invh = ih;
        g_invh[col] = ih;
    }
    __syncthreads();
    const float ih = sh_invh;
    #pragma unroll
    for (int t = 0; t < 4; t++)
        u[tid + 256 * t] *= ih;

    // bitonic sort ascending, 1024 elements, 256 threads
    for (int kk2 = 2; kk2 <= B_ROWS; kk2 <<= 1) {
        for (int jj = kk2 >> 1; jj > 0; jj >>= 1) {
            __syncthreads();
            #pragma unroll
            for (int t = 0; t < 4; t++) {
                int i = tid + 256 * t;
                int ixj = i ^ jj;
                if (ixj > i) {
                    bool up = ((i & kk2) == 0);
                    float a = u[i], b = u[ixj];
                    if ((a > b) == up) { u[i] = b; u[ixj] = a; }
                }
            }
        }
    }
    __syncthreads();
    #pragma unroll
    for (int t = 0; t < 4; t++)
        g_cols[col * B_ROWS + tid + 256 * t] = u[tid + 256 * t];
}

// ---------------------------------------------------------------------------
// Kernel 3: KDE marginal entropies with windowed truncation.
// grid = (64 cols, 16 chunks), block = 64 (2 warps, 1 query/lane)
// ---------------------------------------------------------------------------
__device__ __forceinline__ int lbound(const float* u, float v) {
    int lo = 0, hi = B_ROWS;
    #pragma unroll 1
    while (lo < hi) {
        int mid = (lo + hi) >> 1;
        if (u[mid] < v) lo = mid + 1; else hi = mid;
    }
    return lo;
}

__global__ void kde_kernel() {
    __shared__ float u[B_ROWS];
    __shared__ float red2[2];

    const int tid   = threadIdx.x;
    const int col   = blockIdx.x;
    const int chunk = blockIdx.y;
    const int lane  = tid & 31;
    const int w     = tid >> 5;

    // coalesced load of sorted column
    const float4* gc = (const float4*)(g_cols + col * B_ROWS);
    #pragma unroll
    for (int t = 0; t < 4; t++)
        ((float4*)u)[tid + 64 * t] = gc[tid + 64 * t];
    __syncthreads();

    const float ih = g_invh[col];
    const int base = chunk * 64 + w * 32;
    const float x    = u[base + lane];
    const float xmin = u[base];
    const float xmax = u[base + 31];

    const float K2 = -0.72134752f;          // -0.5 * log2(e)
    const float c2 = 2.0f * ih;             // reflection offset in bandwidth units

    const int a0 = lbound(u, xmin - THRESH);
    const int b0 = lbound(u, xmax + THRESH);
    const int bL = lbound(u, THRESH - xmin);
    const int aR = lbound(u, c2 - THRESH - xmax);

    // main term
    float A0 = 0.f, A1 = 0.f, A2 = 0.f, A3 = 0.f;
    int j = a0;
    for (; j + 3 < b0; j += 4) {
        float t0 = x - u[j + 0];
        float t1 = x - u[j + 1];
        float t2 = x - u[j + 2];
        float t3 = x - u[j + 3];
        A0 += ex2(fmaxf(K2 * t0 * t0, -126.f));
        A1 += ex2(fmaxf(K2 * t1 * t1, -126.f));
        A2 += ex2(fmaxf(K2 * t2 * t2, -126.f));
        A3 += ex2(fmaxf(K2 * t3 * t3, -126.f));
    }
    for (; j < b0; j++) {
        float t0 = x - u[j];
        A0 += ex2(fmaxf(K2 * t0 * t0, -126.f));
    }

    // left reflection (prefix)
    float L0 = 0.f, L1 = 0.f;
    j = 0;
    for (; j + 1 < bL; j += 2) {
        float s0 = x + u[j + 0];
        float s1 = x + u[j + 1];
        L0 += ex2(fmaxf(K2 * s0 * s0, -126.f));
        L1 += ex2(fmaxf(K2 * s1 * s1, -126.f));
    }
    for (; j < bL; j++) {
        float s0 = x + u[j];
        L0 += ex2(fmaxf(K2 * s0 * s0, -126.f));
    }

    // right reflection (suffix)
    float R0 = 0.f, R1 = 0.f;
    j = aR;
    for (; j + 1 < B_ROWS; j += 2) {
        float s0 = x + u[j + 0] - c2;
        float s1 = x + u[j + 1] - c2;
        R0 += ex2(fmaxf(K2 * s0 * s0, -126.f));
        R1 += ex2(fmaxf(K2 * s1 * s1, -126.f));
    }
    for (; j < B_ROWS; j++) {
        float s0 = x + u[j] - c2;
        R0 += ex2(fmaxf(K2 * s0 * s0, -126.f));
    }

    const float Bf = (float)B_ROWS;
    const float scale = ih * (1.0f / (Bf * 2.5066282746310002f));
    float dens = ((A0 + A1) + (A2 + A3) + (L0 + L1) + (R0 + R1)) * scale;
    float l = logf(dens + 1e-8f);

    // block reduce (2 warps)
    #pragma unroll
    for (int off = 16; off; off >>= 1)
        l += __shfl_xor_sync(0xffffffffu, l, off);
    if (lane == 0) red2[w] = l;
    __syncthreads();
    if (tid == 0)
        g_partials[col * QCHUNKS + chunk] = red2[0] + red2[1];
}

// ---------------------------------------------------------------------------
// Kernel 4: assemble output
// ---------------------------------------------------------------------------
__global__ void final_kernel(const int* __restrict__ kp, float* __restrict__ out) {
    __shared__ double dred[256];
    const int tid = threadIdx.x;

    double s = 0.0;
    for (int j = tid; j < B_ROWS; j += 256) s += (double)g_logrho[j];
    dred[tid] = s; __syncthreads();
    for (int st = 128; st > 0; st >>= 1) {
        if (tid < st) dred[tid] += dred[tid + st];
        __syncthreads();
    }

    if (tid == 0) {
        const int k = *kp;
        const double EULER = 0.5772156649015328606;
        double dg_k = -EULER;
        for (int i = 1; i < k; i++) dg_k += 1.0 / (double)i;
        double dg_B = -EULER;
        for (int i = 1; i < B_ROWS; i++) dg_B += 1.0 / (double)i;
        double log_c_d = 0.5 * (double)N_DIM * log(M_PI) - lgamma((double)N_DIM * 0.5 + 1.0);
        double mean_lr = dred[0] / (double)B_ROWS;
        double h_nats = -dg_k + dg_B + log_c_d + (double)N_DIM * 0.5 * mean_lr;
        out[0] = (float)(h_nats / log(2.0));
    }
    if (tid < N_DIM) {
        float t = 0.f;
        #pragma unroll
        for (int c = 0; c < QCHUNKS; c++)
            t += g_partials[tid * QCHUNKS + c];
        out[1 + tid] = -t / (float)B_ROWS;
    }
}

// ---------------------------------------------------------------------------
extern "C" void kernel_launch(void* const* d_in, const int* in_sizes, int n_in,
                              void* d_out, int out_size) {
    const float* act = (const float*)d_in[0];
    const int*   kp  = (const int*)d_in[1];
    float* out = (float*)d_out;
    (void)in_sizes; (void)n_in; (void)out_size;

    prep_kernel<<<N_DIM, 256>>>(act);
    knn_kernel<<<B_ROWS / 8, 256>>>(act, kp);
    dim3 g(N_DIM, QCHUNKS);
    kde_kernel<<<g, 64>>>();
    final_kernel<<<1, 256>>>(kp, out);
}

// round 3
// speedup vs baseline: 2.5768x; 1.6722x over previous
#include <cuda_runtime.h>
#include <math.h>

#define N_DIM   64
#define B_ROWS  1024
#define QCHUNKS 16                 // kde query chunks of 64
#define THRESH  6.5f               // truncation radius in bandwidth units: exp(-21.1) dropped

// Scratch (device globals — no allocation allowed)
__device__ float g_logrho[B_ROWS];
__device__ float g_cols[N_DIM * B_ROWS];     // sorted, scaled (x/h) columns
__device__ float g_invh[N_DIM];
__device__ float g_partials[N_DIM * QCHUNKS];

__device__ __forceinline__ float ex2(float x) {
    float r;
    asm("ex2.approx.ftz.f32 %0, %1;" : "=f"(r) : "f"(x));
    return r;
}

// ---------------------------------------------------------------------------
// Kernel 1: kNN — one warp per row, register top-8, warp-shuffle merge.
// grid = 128, block = 256 (8 warps -> 8 rows)
// ---------------------------------------------------------------------------
__global__ __launch_bounds__(256, 1)
void knn_kernel(const float* __restrict__ act, const int* __restrict__ kp) {
    __shared__ float tile[128][68];        // stride 68 floats: conflict-free LDS.128
    __shared__ float xq[8][N_DIM];

    const int tid  = threadIdx.x;
    const int lane = tid & 31;
    const int w    = tid >> 5;             // warp id = local row
    const int row0 = blockIdx.x * 8;

    // load this block's 8 query rows into shared
    for (int idx = tid; idx < 8 * N_DIM; idx += 256)
        xq[idx >> 6][idx & 63] = act[(row0 + (idx >> 6)) * N_DIM + (idx & 63)];

    float m[8];
    #pragma unroll
    for (int i = 0; i < 8; i++) m[i] = 3.4e38f;

    for (int tb = 0; tb < B_ROWS; tb += 128) {
        __syncthreads();
        // cooperative coalesced tile load (128 rows x 64 dims), float4
        const float4* gsrc = (const float4*)(act + tb * N_DIM);
        #pragma unroll
        for (int t = 0; t < 8; t++) {
            int fi = tid + t * 256;        // 0..2047 float4s
            int r  = fi >> 4;
            int c  = fi & 15;
            *((float4*)&tile[r][c * 4]) = gsrc[fi];
        }
        __syncthreads();

        float acc[4] = {0.f, 0.f, 0.f, 0.f};
        #pragma unroll
        for (int c = 0; c < 4; c++) {      // 4 chunks of 16 dims
            const float4 q0 = *(const float4*)&xq[w][c * 16 + 0];
            const float4 q1 = *(const float4*)&xq[w][c * 16 + 4];
            const float4 q2 = *(const float4*)&xq[w][c * 16 + 8];
            const float4 q3 = *(const float4*)&xq[w][c * 16 + 12];
            #pragma unroll
            for (int s = 0; s < 4; s++) {
                const int j = lane + 32 * s;
                const float4 b0 = *(const float4*)&tile[j][c * 16 + 0];
                const float4 b1 = *(const float4*)&tile[j][c * 16 + 4];
                const float4 b2 = *(const float4*)&tile[j][c * 16 + 8];
                const float4 b3 = *(const float4*)&tile[j][c * 16 + 12];
                float a = acc[s];
                float d;
                d = q0.x - b0.x; a = fmaf(d, d, a);
                d = q0.y - b0.y; a = fmaf(d, d, a);
                d = q0.z - b0.z; a = fmaf(d, d, a);
                d = q0.w - b0.w; a = fmaf(d, d, a);
                d = q1.x - b1.x; a = fmaf(d, d, a);
                d = q1.y - b1.y; a = fmaf(d, d, a);
                d = q1.z - b1.z; a = fmaf(d, d, a);
                d = q1.w - b1.w; a = fmaf(d, d, a);
                d = q2.x - b2.x; a = fmaf(d, d, a);
                d = q2.y - b2.y; a = fmaf(d, d, a);
                d = q2.z - b2.z; a = fmaf(d, d, a);
                d = q2.w - b2.w; a = fmaf(d, d, a);
                d = q3.x - b3.x; a = fmaf(d, d, a);
                d = q3.y - b3.y; a = fmaf(d, d, a);
                d = q3.z - b3.z; a = fmaf(d, d, a);
                d = q3.w - b3.w; a = fmaf(d, d, a);
                acc[s] = a;
            }
        }

        // insert 4 candidates into per-lane sorted top-8 (registers only)
        #pragma unroll
        for (int s = 0; s < 4; s++) {
            float v = acc[s];
            if (v < m[7]) {
                m[7] = v;
                #pragma unroll
                for (int i = 7; i > 0; i--) {
                    if (m[i] < m[i - 1]) { float t2 = m[i]; m[i] = m[i - 1]; m[i - 1] = t2; }
                }
            }
        }
    }

    // warp merge: extract (k+1) global minima from 32 sorted lists
    const int kk = *kp;
    float rho = 0.f;
    for (int r = 0; r <= kk && r < 8; r++) {
        float mv = m[0];
        #pragma unroll
        for (int off = 16; off; off >>= 1)
            mv = fminf(mv, __shfl_xor_sync(0xffffffffu, mv, off));
        rho = mv;
        unsigned msk = __ballot_sync(0xffffffffu, m[0] == mv);
        if (lane == (__ffs(msk) - 1)) {
            #pragma unroll
            for (int i = 0; i < 7; i++) m[i] = m[i + 1];
            m[7] = 3.4e38f;
        }
    }
    if (lane == 0)
        g_logrho[row0 + w] = logf(fmaxf(rho, 1e-12f));
}

// ---------------------------------------------------------------------------
// Kernel 2: per-column prep — std -> h, scale by 1/h, bitonic sort, store.
// grid = 64, block = 256
// ---------------------------------------------------------------------------
__global__ void prep_kernel(const float* __restrict__ act) {
    __shared__ float u[B_ROWS];
    __shared__ float red[256];
    __shared__ float sh_invh;

    const int tid = threadIdx.x;
    const int col = blockIdx.x;

    float s1 = 0.f, s2 = 0.f;
    #pragma unroll
    for (int t = 0; t < 4; t++) {
        float v = act[(tid + 256 * t) * N_DIM + col];
        u[tid + 256 * t] = v;
        s1 += v;
        s2 += v * v;
    }
    // reduce s1
    red[tid] = s1; __syncthreads();
    for (int st = 128; st > 0; st >>= 1) {
        if (tid < st) red[tid] += red[tid + st];
        __syncthreads();
    }
    float tot1 = red[0]; __syncthreads();
    red[tid] = s2; __syncthreads();
    for (int st = 128; st > 0; st >>= 1) {
        if (tid < st) red[tid] += red[tid + st];
        __syncthreads();
    }
    if (tid == 0) {
        const float Bf = (float)B_ROWS;
        float mean = tot1 / Bf;
        float var  = (red[0] - Bf * mean * mean) / (Bf - 1.0f);
        float stdv = sqrtf(fmaxf(var, 0.f));
        float h    = fmaxf(1.06f * stdv * 0.25f, 1e-4f);  // 1024^(-0.2) = 0.25
        float ih   = 1.0f / h;
        sh_invh = ih;
        g_invh[col] = ih;
    }
    __syncthreads();
    const float ih = sh_invh;
    #pragma unroll
    for (int t = 0; t < 4; t++)
        u[tid + 256 * t] *= ih;

    // bitonic sort ascending, 1024 elements, 256 threads
    for (int kk2 = 2; kk2 <= B_ROWS; kk2 <<= 1) {
        for (int jj = kk2 >> 1; jj > 0; jj >>= 1) {
            __syncthreads();
            #pragma unroll
            for (int t = 0; t < 4; t++) {
                int i = tid + 256 * t;
                int ixj = i ^ jj;
                if (ixj > i) {
                    bool up = ((i & kk2) == 0);
                    float a = u[i], b = u[ixj];
                    if ((a > b) == up) { u[i] = b; u[ixj] = a; }
                }
            }
        }
    }
    __syncthreads();
    #pragma unroll
    for (int t = 0; t < 4; t++)
        g_cols[col * B_ROWS + tid + 256 * t] = u[tid + 256 * t];
}

// ---------------------------------------------------------------------------
// Kernel 3: KDE marginal entropies with windowed truncation.
// grid = (64 cols, 16 chunks), block = 64 (2 warps, 1 query/lane)
// ---------------------------------------------------------------------------
__device__ __forceinline__ int lbound(const float* u, float v) {
    int lo = 0, hi = B_ROWS;
    #pragma unroll 1
    while (lo < hi) {
        int mid = (lo + hi) >> 1;
        if (u[mid] < v) lo = mid + 1; else hi = mid;
    }
    return lo;
}

__global__ void kde_kernel() {
    __shared__ float u[B_ROWS];
    __shared__ float red2[2];

    const int tid   = threadIdx.x;
    const int col   = blockIdx.x;
    const int chunk = blockIdx.y;
    const int lane  = tid & 31;
    const int w     = tid >> 5;

    // coalesced load of sorted column
    const float4* gc = (const float4*)(g_cols + col * B_ROWS);
    #pragma unroll
    for (int t = 0; t < 4; t++)
        ((float4*)u)[tid + 64 * t] = gc[tid + 64 * t];
    __syncthreads();

    const float ih = g_invh[col];
    const int base = chunk * 64 + w * 32;
    const float x    = u[base + lane];
    const float xmin = u[base];
    const float xmax = u[base + 31];

    const float K2 = -0.72134752f;          // -0.5 * log2(e)
    const float c2 = 2.0f * ih;             // reflection offset in bandwidth units

    const int a0 = lbound(u, xmin - THRESH);
    const int b0 = lbound(u, xmax + THRESH);
    const int bL = lbound(u, THRESH - xmin);
    const int aR = lbound(u, c2 - THRESH - xmax);

    // main term
    float A0 = 0.f, A1 = 0.f, A2 = 0.f, A3 = 0.f;
    int j = a0;
    for (; j + 3 < b0; j += 4) {
        float t0 = x - u[j + 0];
        float t1 = x - u[j + 1];
        float t2 = x - u[j + 2];
        float t3 = x - u[j + 3];
        A0 += ex2(fmaxf(K2 * t0 * t0, -126.f));
        A1 += ex2(fmaxf(K2 * t1 * t1, -126.f));
        A2 += ex2(fmaxf(K2 * t2 * t2, -126.f));
        A3 += ex2(fmaxf(K2 * t3 * t3, -126.f));
    }
    for (; j < b0; j++) {
        float t0 = x - u[j];
        A0 += ex2(fmaxf(K2 * t0 * t0, -126.f));
    }

    // left reflection (prefix)
    float L0 = 0.f, L1 = 0.f;
    j = 0;
    for (; j + 1 < bL; j += 2) {
        float s0 = x + u[j + 0];
        float s1 = x + u[j + 1];
        L0 += ex2(fmaxf(K2 * s0 * s0, -126.f));
        L1 += ex2(fmaxf(K2 * s1 * s1, -126.f));
    }
    for (; j < bL; j++) {
        float s0 = x + u[j];
        L0 += ex2(fmaxf(K2 * s0 * s0, -126.f));
    }

    // right reflection (suffix)
    float R0 = 0.f, R1 = 0.f;
    j = aR;
    for (; j + 1 < B_ROWS; j += 2) {
        float s0 = x + u[j + 0] - c2;
        float s1 = x + u[j + 1] - c2;
        R0 += ex2(fmaxf(K2 * s0 * s0, -126.f));
        R1 += ex2(fmaxf(K2 * s1 * s1, -126.f));
    }
    for (; j < B_ROWS; j++) {
        float s0 = x + u[j] - c2;
        R0 += ex2(fmaxf(K2 * s0 * s0, -126.f));
    }

    const float Bf = (float)B_ROWS;
    const float scale = ih * (1.0f / (Bf * 2.5066282746310002f));
    float dens = ((A0 + A1) + (A2 + A3) + (L0 + L1) + (R0 + R1)) * scale;
    float l = logf(dens + 1e-8f);

    // block reduce (2 warps)
    #pragma unroll
    for (int off = 16; off; off >>= 1)
        l += __shfl_xor_sync(0xffffffffu, l, off);
    if (lane == 0) red2[w] = l;
    __syncthreads();
    if (tid == 0)
        g_partials[col * QCHUNKS + chunk] = red2[0] + red2[1];
}

// ---------------------------------------------------------------------------
// Kernel 4: assemble output (all transcendental constants precomputed;
// only psi(k) depends on runtime k — a (k-1)-iteration loop)
// ---------------------------------------------------------------------------
__global__ void final_kernel(const int* __restrict__ kp, float* __restrict__ out) {
    __shared__ double dred[256];
    const int tid = threadIdx.x;

    double s = 0.0;
    for (int j = tid; j < B_ROWS; j += 256) s += (double)g_logrho[j];
    dred[tid] = s; __syncthreads();
    for (int st = 128; st > 0; st >>= 1) {
        if (tid < st) dred[tid] += dred[tid + st];
        __syncthreads();
    }

    if (tid == 0) {
        const int k = *kp;
        const double EULER   = 0.5772156649015328606;
        const double DG_B    = 6.9309834448765934;     // psi(1024)
        const double LGAMMA33 = 81.55795945611503558;  // lgamma(64/2 + 1)
        const double LOG_PI  = 1.1447298858494001741;
        const double INV_LN2 = 1.4426950408889634074;
        double dg_k = -EULER;
        for (int i = 1; i < k; i++) dg_k += 1.0 / (double)i;
        double log_c_d = 0.5 * (double)N_DIM * LOG_PI - LGAMMA33;
        double mean_lr = dred[0] / (double)B_ROWS;
        double h_nats = -dg_k + DG_B + log_c_d + (double)N_DIM * 0.5 * mean_lr;
        out[0] = (float)(h_nats * INV_LN2);
    }
    if (tid < N_DIM) {
        float t = 0.f;
        #pragma unroll
        for (int c = 0; c < QCHUNKS; c++)
            t += g_partials[tid * QCHUNKS + c];
        out[1 + tid] = -t / (float)B_ROWS;
    }
}

// ---------------------------------------------------------------------------
extern "C" void kernel_launch(void* const* d_in, const int* in_sizes, int n_in,
                              void* d_out, int out_size) {
    const float* act = (const float*)d_in[0];
    const int*   kp  = (const int*)d_in[1];
    float* out = (float*)d_out;
    (void)in_sizes; (void)n_in; (void)out_size;

    prep_kernel<<<N_DIM, 256>>>(act);
    knn_kernel<<<B_ROWS / 8, 256>>>(act, kp);
    dim3 g(N_DIM, QCHUNKS);
    kde_kernel<<<g, 64>>>();
    final_kernel<<<1, 256>>>(kp, out);
}

// round 4
// speedup vs baseline: 3.2297x; 1.2534x over previous
#include <cuda_runtime.h>
#include <math.h>

#define N_DIM    64
#define B_ROWS   1024
#define QCH      32                // kde chunks of 32 queries per block
#define NBLK_KDE (N_DIM * QCH)     // 2048
#define THRESH   4.0f              // truncation radius: erfc(4/sqrt2)=6.3e-5 rel mass dropped

// Scratch (device globals — no allocation allowed)
__device__ float g_logrho[B_ROWS];
__device__ float g_cols[N_DIM * B_ROWS];   // sorted, scaled (x/h) columns
__device__ float g_invh[N_DIM];
__device__ float g_partials[N_DIM * QCH];
__device__ int   g_done;

__device__ __forceinline__ float ex2(float x) {
    float r;
    asm("ex2.approx.ftz.f32 %0, %1;" : "=f"(r) : "f"(x));
    return r;
}

// ---------------------------------------------------------------------------
// Kernel 1: fused prep (blocks 0..63) + knn (blocks 64..191). Independent
// subtasks run concurrently across SMs in one launch.
// ---------------------------------------------------------------------------
__global__ __launch_bounds__(256, 1)
void fused_prep_knn(const float* __restrict__ act, const int* __restrict__ kp) {
    __shared__ float tile[128][68];      // knn: stride 17 float4s -> conflict-free LDS.128
    __shared__ float xq[8][N_DIM];       // knn
    __shared__ float u[B_ROWS];          // prep
    __shared__ float red[256];           // prep
    __shared__ float sh_invh;            // prep

    const int tid = threadIdx.x;
    const int bx  = blockIdx.x;

    if (bx == 0 && tid == 0) g_done = 0;   // reset completion counter for this run

    if (bx < N_DIM) {
        // ================= PREP: column std -> h, scale, bitonic sort ======
        const int col = bx;
        float s1 = 0.f, s2 = 0.f;
        #pragma unroll
        for (int t = 0; t < 4; t++) {
            float v = act[(tid + 256 * t) * N_DIM + col];
            u[tid + 256 * t] = v;
            s1 += v;
            s2 += v * v;
        }
        red[tid] = s1; __syncthreads();
        for (int st = 128; st > 0; st >>= 1) {
            if (tid < st) red[tid] += red[tid + st];
            __syncthreads();
        }
        float tot1 = red[0]; __syncthreads();
        red[tid] = s2; __syncthreads();
        for (int st = 128; st > 0; st >>= 1) {
            if (tid < st) red[tid] += red[tid + st];
            __syncthreads();
        }
        if (tid == 0) {
            const float Bf = (float)B_ROWS;
            float mean = tot1 / Bf;
            float var  = (red[0] - Bf * mean * mean) / (Bf - 1.0f);
            float stdv = sqrtf(fmaxf(var, 0.f));
            float h    = fmaxf(1.06f * stdv * 0.25f, 1e-4f);   // 1024^-0.2 = 0.25
            float ih   = 1.0f / h;
            sh_invh = ih;
            g_invh[col] = ih;
        }
        __syncthreads();
        const float ih = sh_invh;
        #pragma unroll
        for (int t = 0; t < 4; t++)
            u[tid + 256 * t] *= ih;

        // bitonic sort ascending (1024 elems, 256 threads)
        for (int kk2 = 2; kk2 <= B_ROWS; kk2 <<= 1) {
            for (int jj = kk2 >> 1; jj > 0; jj >>= 1) {
                __syncthreads();
                #pragma unroll
                for (int t = 0; t < 4; t++) {
                    int i = tid + 256 * t;
                    int ixj = i ^ jj;
                    if (ixj > i) {
                        bool up = ((i & kk2) == 0);
                        float a = u[i], b = u[ixj];
                        if ((a > b) == up) { u[i] = b; u[ixj] = a; }
                    }
                }
            }
        }
        __syncthreads();
        #pragma unroll
        for (int t = 0; t < 4; t++)
            g_cols[col * B_ROWS + tid + 256 * t] = u[tid + 256 * t];
    } else {
        // ================= KNN: one warp per row =========================
        const int lane = tid & 31;
        const int w    = tid >> 5;
        const int row0 = (bx - N_DIM) * 8;

        for (int idx = tid; idx < 8 * N_DIM; idx += 256)
            xq[idx >> 6][idx & 63] = act[(row0 + (idx >> 6)) * N_DIM + (idx & 63)];

        float m[8];
        #pragma unroll
        for (int i = 0; i < 8; i++) m[i] = 3.4e38f;

        for (int tb = 0; tb < B_ROWS; tb += 128) {
            __syncthreads();
            const float4* gsrc = (const float4*)(act + tb * N_DIM);
            #pragma unroll
            for (int t = 0; t < 8; t++) {
                int fi = tid + t * 256;
                int r  = fi >> 4;
                int c  = fi & 15;
                *((float4*)&tile[r][c * 4]) = gsrc[fi];
            }
            __syncthreads();

            float acc[4] = {0.f, 0.f, 0.f, 0.f};
            #pragma unroll
            for (int c = 0; c < 4; c++) {
                const float4 q0 = *(const float4*)&xq[w][c * 16 + 0];
                const float4 q1 = *(const float4*)&xq[w][c * 16 + 4];
                const float4 q2 = *(const float4*)&xq[w][c * 16 + 8];
                const float4 q3 = *(const float4*)&xq[w][c * 16 + 12];
                #pragma unroll
                for (int s = 0; s < 4; s++) {
                    const int j = lane + 32 * s;
                    const float4 b0 = *(const float4*)&tile[j][c * 16 + 0];
                    const float4 b1 = *(const float4*)&tile[j][c * 16 + 4];
                    const float4 b2 = *(const float4*)&tile[j][c * 16 + 8];
                    const float4 b3 = *(const float4*)&tile[j][c * 16 + 12];
                    float a = acc[s];
                    float d;
                    d = q0.x - b0.x; a = fmaf(d, d, a);
                    d = q0.y - b0.y; a = fmaf(d, d, a);
                    d = q0.z - b0.z; a = fmaf(d, d, a);
                    d = q0.w - b0.w; a = fmaf(d, d, a);
                    d = q1.x - b1.x; a = fmaf(d, d, a);
                    d = q1.y - b1.y; a = fmaf(d, d, a);
                    d = q1.z - b1.z; a = fmaf(d, d, a);
                    d = q1.w - b1.w; a = fmaf(d, d, a);
                    d = q2.x - b2.x; a = fmaf(d, d, a);
                    d = q2.y - b2.y; a = fmaf(d, d, a);
                    d = q2.z - b2.z; a = fmaf(d, d, a);
                    d = q2.w - b2.w; a = fmaf(d, d, a);
                    d = q3.x - b3.x; a = fmaf(d, d, a);
                    d = q3.y - b3.y; a = fmaf(d, d, a);
                    d = q3.z - b3.z; a = fmaf(d, d, a);
                    d = q3.w - b3.w; a = fmaf(d, d, a);
                    acc[s] = a;
                }
            }
            #pragma unroll
            for (int s = 0; s < 4; s++) {
                float v = acc[s];
                if (v < m[7]) {
                    m[7] = v;
                    #pragma unroll
                    for (int i = 7; i > 0; i--) {
                        if (m[i] < m[i - 1]) { float t2 = m[i]; m[i] = m[i - 1]; m[i - 1] = t2; }
                    }
                }
            }
        }

        const int kk = *kp;
        float rho = 0.f;
        for (int r = 0; r <= kk && r < 8; r++) {
            float mv = m[0];
            #pragma unroll
            for (int off = 16; off; off >>= 1)
                mv = fminf(mv, __shfl_xor_sync(0xffffffffu, mv, off));
            rho = mv;
            unsigned msk = __ballot_sync(0xffffffffu, m[0] == mv);
            if (lane == (__ffs(msk) - 1)) {
                #pragma unroll
                for (int i = 0; i < 7; i++) m[i] = m[i + 1];
                m[7] = 3.4e38f;
            }
        }
        if (lane == 0)
            g_logrho[row0 + w] = logf(fmaxf(rho, 1e-12f));
    }
}

// ---------------------------------------------------------------------------
// Kernel 2: KDE (windowed, j split over 4 warps) + fused final assembly.
// grid = (64 cols, 32 chunks), block = 128. Last block writes all 65 outputs.
// ---------------------------------------------------------------------------
__device__ __forceinline__ int lbound(const float* u, float v) {
    int lo = 0, hi = B_ROWS;
    #pragma unroll 1
    while (lo < hi) {
        int mid = (lo + hi) >> 1;
        if (u[mid] < v) lo = mid + 1; else hi = mid;
    }
    return lo;
}

__global__ __launch_bounds__(128, 16)
void kde_final_kernel(const int* __restrict__ kp, float* __restrict__ out) {
    __shared__ float u[B_ROWS];
    __shared__ float sums[32][5];       // [query lane][warp], pad 5 vs bank conflict
    __shared__ double dred[128];
    __shared__ int sdone;

    const int tid   = threadIdx.x;
    const int lane  = tid & 31;
    const int w     = tid >> 5;         // 0..3: j-stride offset
    const int col   = blockIdx.x;
    const int chunk = blockIdx.y;

    const float4* gc = (const float4*)(g_cols + col * B_ROWS);
    #pragma unroll
    for (int t = 0; t < 2; t++)
        ((float4*)u)[tid + 128 * t] = gc[tid + 128 * t];
    __syncthreads();

    const float ih = g_invh[col];
    const int   q0 = chunk * 32;
    const float x    = u[q0 + lane];
    const float xmin = u[q0];
    const float xmax = u[q0 + 31];

    const float K2 = -0.72134752f;      // -0.5 * log2(e)
    const float c2 = 2.0f * ih;

    const int a0 = lbound(u, xmin - THRESH);
    const int b0 = lbound(u, xmax + THRESH);
    const int bL = lbound(u, THRESH - xmin);
    const int aR = lbound(u, c2 - THRESH - xmax);

    float A0 = 0.f, A1 = 0.f;
    int j = a0 + w;
    for (; j + 4 < b0; j += 8) {
        float t0 = x - u[j];
        float t1 = x - u[j + 4];
        A0 += ex2(K2 * t0 * t0);
        A1 += ex2(K2 * t1 * t1);
    }
    for (; j < b0; j += 4) {
        float t0 = x - u[j];
        A0 += ex2(K2 * t0 * t0);
    }
    for (j = w; j < bL; j += 4) {
        float s = x + u[j];
        A1 += ex2(K2 * s * s);
    }
    for (j = aR + w; j < B_ROWS; j += 4) {
        float s = x + u[j] - c2;
        A0 += ex2(K2 * s * s);
    }
    sums[lane][w] = A0 + A1;
    __syncthreads();

    if (w == 0) {
        const float Bf = (float)B_ROWS;
        const float scale = ih * (1.0f / (Bf * 2.5066282746310002f));
        float tot = (sums[lane][0] + sums[lane][1]) + (sums[lane][2] + sums[lane][3]);
        float l = logf(tot * scale + 1e-8f);
        #pragma unroll
        for (int off = 16; off; off >>= 1)
            l += __shfl_xor_sync(0xffffffffu, l, off);
        if (lane == 0)
            g_partials[col * QCH + chunk] = l;
    }
    __syncthreads();

    // completion counter: last block assembles outputs
    if (tid == 0) {
        __threadfence();
        unsigned p = atomicAdd(&g_done, 1);
        sdone = (p == NBLK_KDE - 1);
    }
    __syncthreads();
    if (!sdone) return;
    __threadfence();

    // marginals
    if (tid < N_DIM) {
        float t = 0.f;
        #pragma unroll
        for (int c = 0; c < QCH; c++)
            t += g_partials[tid * QCH + c];
        out[1 + tid] = -t / (float)B_ROWS;
    }
    // joint entropy (fp64, precomputed constants; psi(k) loop only)
    double s = 0.0;
    for (int i = tid; i < B_ROWS; i += 128) s += (double)g_logrho[i];
    dred[tid] = s; __syncthreads();
    for (int st = 64; st > 0; st >>= 1) {
        if (tid < st) dred[tid] += dred[tid + st];
        __syncthreads();
    }
    if (tid == 0) {
        const int k = *kp;
        const double EULER    = 0.5772156649015328606;
        const double DG_B     = 6.9309834448765934;     // psi(1024)
        const double LGAMMA33 = 81.55795945611503558;   // lgamma(64/2 + 1)
        const double LOG_PI   = 1.1447298858494001741;
        const double INV_LN2  = 1.4426950408889634074;
        double dg_k = -EULER;
        for (int i = 1; i < k; i++) dg_k += 1.0 / (double)i;
        double log_c_d = 0.5 * (double)N_DIM * LOG_PI - LGAMMA33;
        double mean_lr = dred[0] / (double)B_ROWS;
        double h_nats = -dg_k + DG_B + log_c_d + (double)N_DIM * 0.5 * mean_lr;
        out[0] = (float)(h_nats * INV_LN2);
    }
}

// ---------------------------------------------------------------------------
extern "C" void kernel_launch(void* const* d_in, const int* in_sizes, int n_in,
                              void* d_out, int out_size) {
    const float* act = (const float*)d_in[0];
    const int*   kp  = (const int*)d_in[1];
    float* out = (float*)d_out;
    (void)in_sizes; (void)n_in; (void)out_size;

    fused_prep_knn<<<N_DIM + B_ROWS / 8, 256>>>(act, kp);
    dim3 g(N_DIM, QCH);
    kde_final_kernel<<<g, 128>>>(kp, out);
}

// round 5
// speedup vs baseline: 3.6537x; 1.1313x over previous
#include <cuda_runtime.h>
#include <math.h>

#define N_DIM    64
#define B_ROWS   1024
#define QCH      32                 // kde chunks of 32 queries
#define NBLK_KDE (N_DIM * QCH)      // 2048
#define ZF       0.84932157f        // sqrt(0.5*log2(e)); ex2(-(ZF*a)^2) == exp(-a^2/2)
#define TS4      3.39728628f        // 4.0 * ZF  (truncation radius 4 h-units, scaled)

// Scratch (device globals — no allocation allowed)
__device__ float g_logrho[B_ROWS];
__device__ float g_cols[N_DIM * B_ROWS];   // sorted columns, scaled by ZF/h
__device__ float g_invh[N_DIM];
__device__ float g_zih[N_DIM];             // ZF/h per column
__device__ float g_partials[N_DIM * QCH];
__device__ float g_t8[64][2][16][8];       // [rowgroup][j-half][row][top8]
__device__ int   g_pairc[64];              // self-resetting pair counters
__device__ int   g_done;

__device__ __forceinline__ float ex2(float x) {
    float r;
    asm("ex2.approx.ftz.f32 %0, %1;" : "=f"(r) : "f"(x));
    return r;
}

// ---------------------------------------------------------------------------
// Kernel 1: fused prep (blocks 0..63) + knn (blocks 64..191).
// knn: block i-64 -> rowgroup g=(i-64)>>1 (16 rows), j-half=(i-64)&1 (512 js).
// Each warp owns 2 rows; distances via norm trick; per-pair counter merges.
// ---------------------------------------------------------------------------
__global__ __launch_bounds__(256)
void fused_prep_knn(const float* __restrict__ act, const int* __restrict__ kp) {
    __shared__ float tile[128][68];      // conflict-free LDS.128
    __shared__ float xq[16][N_DIM];
    __shared__ float jn[128];
    __shared__ float u[B_ROWS];
    __shared__ float red[256];
    __shared__ float sh_scale;
    __shared__ int   sh_merge;

    const int tid = threadIdx.x;
    const int bx  = blockIdx.x;

    if (bx == 0 && tid == 0) g_done = 0;

    if (bx < N_DIM) {
        // ================= PREP ===========================================
        const int col = bx;
        float s1 = 0.f, s2 = 0.f;
        #pragma unroll
        for (int t = 0; t < 4; t++) {
            float v = act[(tid + 256 * t) * N_DIM + col];
            u[tid + 256 * t] = v;
            s1 += v;
            s2 += v * v;
        }
        red[tid] = s1; __syncthreads();
        for (int st = 128; st > 0; st >>= 1) {
            if (tid < st) red[tid] += red[tid + st];
            __syncthreads();
        }
        float tot1 = red[0]; __syncthreads();
        red[tid] = s2; __syncthreads();
        for (int st = 128; st > 0; st >>= 1) {
            if (tid < st) red[tid] += red[tid + st];
            __syncthreads();
        }
        if (tid == 0) {
            const float Bf = (float)B_ROWS;
            float mean = tot1 / Bf;
            float var  = (red[0] - Bf * mean * mean) / (Bf - 1.0f);
            float stdv = sqrtf(fmaxf(var, 0.f));
            float h    = fmaxf(1.06f * stdv * 0.25f, 1e-4f);   // 1024^-0.2=0.25
            float ih   = 1.0f / h;
            g_invh[col] = ih;
            g_zih[col]  = ih * ZF;
            sh_scale    = ih * ZF;
        }
        __syncthreads();
        const float sc = sh_scale;
        #pragma unroll
        for (int t = 0; t < 4; t++)
            u[tid + 256 * t] *= sc;

        for (int kk2 = 2; kk2 <= B_ROWS; kk2 <<= 1) {
            for (int jj = kk2 >> 1; jj > 0; jj >>= 1) {
                __syncthreads();
                #pragma unroll
                for (int t = 0; t < 4; t++) {
                    int i = tid + 256 * t;
                    int ixj = i ^ jj;
                    if (ixj > i) {
                        bool up = ((i & kk2) == 0);
                        float a = u[i], b = u[ixj];
                        if ((a > b) == up) { u[i] = b; u[ixj] = a; }
                    }
                }
            }
        }
        __syncthreads();
        #pragma unroll
        for (int t = 0; t < 4; t++)
            g_cols[col * B_ROWS + tid + 256 * t] = u[tid + 256 * t];
    } else {
        // ================= KNN ============================================
        const int i    = bx - N_DIM;          // 0..127
        const int g    = i >> 1;
        const int half = i & 1;
        const int row0 = g * 16;
        const int lane = tid & 31;
        const int w    = tid >> 5;

        for (int idx = tid; idx < 16 * N_DIM; idx += 256)
            xq[idx >> 6][idx & 63] = act[(row0 + (idx >> 6)) * N_DIM + (idx & 63)];
        __syncthreads();

        // query norms for this warp's 2 rows
        float qa, qb;
        {
            float a0 = xq[2 * w][2 * lane], a1 = xq[2 * w][2 * lane + 1];
            float b0 = xq[2 * w + 1][2 * lane], b1 = xq[2 * w + 1][2 * lane + 1];
            qa = a0 * a0 + a1 * a1;
            qb = b0 * b0 + b1 * b1;
            #pragma unroll
            for (int off = 16; off; off >>= 1) {
                qa += __shfl_xor_sync(0xffffffffu, qa, off);
                qb += __shfl_xor_sync(0xffffffffu, qb, off);
            }
        }

        float mA[8], mB[8];
        #pragma unroll
        for (int q = 0; q < 8; q++) { mA[q] = 3.4e38f; mB[q] = 3.4e38f; }

        for (int t = 0; t < 4; t++) {
            const int tb = half * 512 + t * 128;
            __syncthreads();
            const float4* gsrc = (const float4*)(act + tb * N_DIM);
            #pragma unroll
            for (int tt = 0; tt < 8; tt++) {
                int fi = tid + tt * 256;
                int r  = fi >> 4;
                int c  = fi & 15;
                *((float4*)&tile[r][c * 4]) = gsrc[fi];
            }
            __syncthreads();
            if (tid < 128) {
                float s = 0.f;
                #pragma unroll
                for (int c = 0; c < 16; c++) {
                    float4 v = *(const float4*)&tile[tid][c * 4];
                    s += v.x * v.x + v.y * v.y + v.z * v.z + v.w * v.w;
                }
                jn[tid] = s;
            }
            __syncthreads();

            float dA[4] = {0.f, 0.f, 0.f, 0.f};
            float dB[4] = {0.f, 0.f, 0.f, 0.f};
            #pragma unroll
            for (int c = 0; c < 4; c++) {
                const float4 qA0 = *(const float4*)&xq[2 * w][c * 16 + 0];
                const float4 qA1 = *(const float4*)&xq[2 * w][c * 16 + 4];
                const float4 qA2 = *(const float4*)&xq[2 * w][c * 16 + 8];
                const float4 qA3 = *(const float4*)&xq[2 * w][c * 16 + 12];
                const float4 qB0 = *(const float4*)&xq[2 * w + 1][c * 16 + 0];
                const float4 qB1 = *(const float4*)&xq[2 * w + 1][c * 16 + 4];
                const float4 qB2 = *(const float4*)&xq[2 * w + 1][c * 16 + 8];
                const float4 qB3 = *(const float4*)&xq[2 * w + 1][c * 16 + 12];
                #pragma unroll
                for (int s = 0; s < 4; s++) {
                    const int j = lane + 32 * s;
                    const float4 b0 = *(const float4*)&tile[j][c * 16 + 0];
                    const float4 b1 = *(const float4*)&tile[j][c * 16 + 4];
                    const float4 b2 = *(const float4*)&tile[j][c * 16 + 8];
                    const float4 b3 = *(const float4*)&tile[j][c * 16 + 12];
                    float a = dA[s], b = dB[s];
                    a = fmaf(qA0.x, b0.x, a); b = fmaf(qB0.x, b0.x, b);
                    a = fmaf(qA0.y, b0.y, a); b = fmaf(qB0.y, b0.y, b);
                    a = fmaf(qA0.z, b0.z, a); b = fmaf(qB0.z, b0.z, b);
                    a = fmaf(qA0.w, b0.w, a); b = fmaf(qB0.w, b0.w, b);
                    a = fmaf(qA1.x, b1.x, a); b = fmaf(qB1.x, b1.x, b);
                    a = fmaf(qA1.y, b1.y, a); b = fmaf(qB1.y, b1.y, b);
                    a = fmaf(qA1.z, b1.z, a); b = fmaf(qB1.z, b1.z, b);
                    a = fmaf(qA1.w, b1.w, a); b = fmaf(qB1.w, b1.w, b);
                    a = fmaf(qA2.x, b2.x, a); b = fmaf(qB2.x, b2.x, b);
                    a = fmaf(qA2.y, b2.y, a); b = fmaf(qB2.y, b2.y, b);
                    a = fmaf(qA2.z, b2.z, a); b = fmaf(qB2.z, b2.z, b);
                    a = fmaf(qA2.w, b2.w, a); b = fmaf(qB2.w, b2.w, b);
                    a = fmaf(qA3.x, b3.x, a); b = fmaf(qB3.x, b3.x, b);
                    a = fmaf(qA3.y, b3.y, a); b = fmaf(qB3.y, b3.y, b);
                    a = fmaf(qA3.z, b3.z, a); b = fmaf(qB3.z, b3.z, b);
                    a = fmaf(qA3.w, b3.w, a); b = fmaf(qB3.w, b3.w, b);
                    dA[s] = a; dB[s] = b;
                }
            }
            #pragma unroll
            for (int s = 0; s < 4; s++) {
                const float nj = jn[lane + 32 * s];
                float vA = fmaf(dA[s], -2.f, qa + nj);
                if (vA < mA[7]) {
                    mA[7] = vA;
                    #pragma unroll
                    for (int q = 7; q > 0; q--)
                        if (mA[q] < mA[q - 1]) { float tm = mA[q]; mA[q] = mA[q - 1]; mA[q - 1] = tm; }
                }
                float vB = fmaf(dB[s], -2.f, qb + nj);
                if (vB < mB[7]) {
                    mB[7] = vB;
                    #pragma unroll
                    for (int q = 7; q > 0; q--)
                        if (mB[q] < mB[q - 1]) { float tm = mB[q]; mB[q] = mB[q - 1]; mB[q - 1] = tm; }
                }
            }
        }

        // extract sorted top-8 per query via warp shuffles, store to global
        float myA = 3.4e38f, myB = 3.4e38f;
        for (int r = 0; r < 8; r++) {
            float mv = mA[0];
            #pragma unroll
            for (int off = 16; off; off >>= 1)
                mv = fminf(mv, __shfl_xor_sync(0xffffffffu, mv, off));
            if (lane == r) myA = mv;
            unsigned msk = __ballot_sync(0xffffffffu, mA[0] == mv);
            if (lane == (__ffs(msk) - 1)) {
                #pragma unroll
                for (int q = 0; q < 7; q++) mA[q] = mA[q + 1];
                mA[7] = 3.4e38f;
            }
        }
        for (int r = 0; r < 8; r++) {
            float mv = mB[0];
            #pragma unroll
            for (int off = 16; off; off >>= 1)
                mv = fminf(mv, __shfl_xor_sync(0xffffffffu, mv, off));
            if (lane == r) myB = mv;
            unsigned msk = __ballot_sync(0xffffffffu, mB[0] == mv);
            if (lane == (__ffs(msk) - 1)) {
                #pragma unroll
                for (int q = 0; q < 7; q++) mB[q] = mB[q + 1];
                mB[7] = 3.4e38f;
            }
        }
        if (lane < 8) {
            g_t8[g][half][2 * w][lane]     = myA;
            g_t8[g][half][2 * w + 1][lane] = myB;
        }
        __syncthreads();
        if (tid == 0) {
            __threadfence();
            int old = atomicAdd(&g_pairc[g], 1);
            sh_merge = (old == 1);
        }
        __syncthreads();
        if (sh_merge) {
            __threadfence();
            if (tid < 16) {
                const int k = *kp;
                float a[8], b[8];
                #pragma unroll
                for (int q = 0; q < 8; q++) {
                    a[q] = g_t8[g][0][tid][q];
                    b[q] = g_t8[g][1][tid][q];
                }
                int ia = 0, ib = 0; float v = 0.f;
                for (int t = 0; t <= k && t < 16; t++) {
                    float va = (ia < 8) ? a[ia] : 3.4e38f;
                    float vb = (ib < 8) ? b[ib] : 3.4e38f;
                    if (va <= vb) { v = va; ia++; } else { v = vb; ib++; }
                }
                g_logrho[row0 + tid] = logf(fmaxf(v, 1e-12f));
            }
            if (tid == 0) g_pairc[g] = 0;   // self-reset for graph replay
        }
    }
}

// ---------------------------------------------------------------------------
// Kernel 2: KDE (scaled coords, contiguous per-warp quarters, float2 loads)
// + fused final assembly. grid=(64,32), block=128.
// ---------------------------------------------------------------------------
__device__ __forceinline__ int lbound(const float* u, float v) {
    int lo = 0, hi = B_ROWS;
    #pragma unroll 1
    while (lo < hi) {
        int mid = (lo + hi) >> 1;
        if (u[mid] < v) lo = mid + 1; else hi = mid;
    }
    return lo;
}

__global__ __launch_bounds__(128)
void kde_final_kernel(const int* __restrict__ kp, float* __restrict__ out) {
    __shared__ float u[B_ROWS];
    __shared__ float sums[32][5];
    __shared__ double dred[128];
    __shared__ int sdone;

    const int tid   = threadIdx.x;
    const int lane  = tid & 31;
    const int w     = tid >> 5;
    const int col   = blockIdx.x;
    const int chunk = blockIdx.y;

    const float4* gc = (const float4*)(g_cols + col * B_ROWS);
    #pragma unroll
    for (int t = 0; t < 2; t++)
        ((float4*)u)[tid + 128 * t] = gc[tid + 128 * t];
    __syncthreads();

    const float zih = g_zih[col];
    const int   q0  = chunk * 32;
    const float x    = u[q0 + lane];
    const float xmin = u[q0];
    const float xmax = u[q0 + 31];
    const float c2s  = 2.0f * zih;

    const int a0 = lbound(u, xmin - TS4);
    const int b0 = lbound(u, xmax + TS4);
    const int bL = lbound(u, TS4 - xmin);
    const int aR = lbound(u, c2s - TS4 - xmax);

    // main term: contiguous quarter per warp, float2 loads
    const int len = b0 - a0;
    int lo = a0 + ((len * w) >> 2);
    int hi = a0 + ((len * (w + 1)) >> 2);
    float A0 = 0.f, A1 = 0.f;
    int j = lo;
    if (j < hi && (j & 1)) {
        float d = x - u[j];
        A0 += ex2(__fmaf_rn(d, -d, 0.f));
        j++;
    }
    for (; j + 1 < hi; j += 2) {
        float2 y = *(const float2*)(u + j);
        float d0 = x - y.x;
        float d1 = x - y.y;
        A0 += ex2(__fmaf_rn(d0, -d0, 0.f));
        A1 += ex2(__fmaf_rn(d1, -d1, 0.f));
    }
    if (j < hi) {
        float d = x - u[j];
        A0 += ex2(__fmaf_rn(d, -d, 0.f));
    }
    // reflections (small windows, stride-4 across warps)
    for (j = w; j < bL; j += 4) {
        float s = x + u[j];
        A1 += ex2(__fmaf_rn(s, -s, 0.f));
    }
    for (j = aR + w; j < B_ROWS; j += 4) {
        float s = x + u[j] - c2s;
        A0 += ex2(__fmaf_rn(s, -s, 0.f));
    }
    sums[lane][w] = A0 + A1;
    __syncthreads();

    if (w == 0) {
        const float Bf = (float)B_ROWS;
        const float scale = g_invh[col] * (1.0f / (Bf * 2.5066282746310002f));
        float tot = (sums[lane][0] + sums[lane][1]) + (sums[lane][2] + sums[lane][3]);
        float l = logf(tot * scale + 1e-8f);
        #pragma unroll
        for (int off = 16; off; off >>= 1)
            l += __shfl_xor_sync(0xffffffffu, l, off);
        if (lane == 0)
            g_partials[col * QCH + chunk] = l;
    }
    __syncthreads();

    if (tid == 0) {
        __threadfence();
        unsigned p = atomicAdd(&g_done, 1);
        sdone = (p == NBLK_KDE - 1);
    }
    __syncthreads();
    if (!sdone) return;
    __threadfence();

    if (tid < N_DIM) {
        float t = 0.f;
        #pragma unroll
        for (int c = 0; c < QCH; c++)
            t += g_partials[tid * QCH + c];
        out[1 + tid] = -t / (float)B_ROWS;
    }
    double s = 0.0;
    for (int i = tid; i < B_ROWS; i += 128) s += (double)g_logrho[i];
    dred[tid] = s; __syncthreads();
    for (int st = 64; st > 0; st >>= 1) {
        if (tid < st) dred[tid] += dred[tid + st];
        __syncthreads();
    }
    if (tid == 0) {
        const int k = *kp;
        const double EULER    = 0.5772156649015328606;
        const double DG_B     = 6.9309834448765934;     // psi(1024)
        const double LGAMMA33 = 81.55795945611503558;   // lgamma(64/2+1)
        const double LOG_PI   = 1.1447298858494001741;
        const double INV_LN2  = 1.4426950408889634074;
        double dg_k = -EULER;
        for (int i = 1; i < k; i++) dg_k += 1.0 / (double)i;
        double log_c_d = 0.5 * (double)N_DIM * LOG_PI - LGAMMA33;
        double mean_lr = dred[0] / (double)B_ROWS;
        double h_nats = -dg_k + DG_B + log_c_d + (double)N_DIM * 0.5 * mean_lr;
        out[0] = (float)(h_nats * INV_LN2);
    }
}

// ---------------------------------------------------------------------------
extern "C" void kernel_launch(void* const* d_in, const int* in_sizes, int n_in,
                              void* d_out, int out_size) {
    const float* act = (const float*)d_in[0];
    const int*   kp  = (const int*)d_in[1];
    float* out = (float*)d_out;
    (void)in_sizes; (void)n_in; (void)out_size;

    fused_prep_knn<<<N_DIM + 128, 256>>>(act, kp);
    dim3 g(N_DIM, QCH);
    kde_final_kernel<<<g, 128>>>(kp, out);
}